// round 1
// baseline (speedup 1.0000x reference)
#include <cuda_runtime.h>
#include <math.h>

// ---------------- problem constants ----------------
#define TD      50000      // T_DATA
#define E_NO    2000
#define I_NO    500
#define CCH     63         // SUB-1 channels
#define TN      200        // T_NO
#define OBS_LEN 401        // 2*T_NO+1
#define NB      13         // COS_NB
#define M_PI_D  3.14159265358979323846

// ---------------- device scratch (no allocations allowed) ----------------
__device__ float g_ek[CCH * TN];        // e kernels per channel  ek[c][j]
__device__ float g_ik[CCH * TN];        // i kernels per channel
__device__ float g_ok[CCH * OBS_LEN];   // obs kernels per channel (index j: Z[t+200-j])
__device__ float g_syn_e[CCH * TD];     // transposed syn_e [c][t]
__device__ float g_syn_i[CCH * TD];     // transposed syn_i [c][t]

// ============================================================
// Kernel 0: build temporal kernels from bases (double, as numpy)
// ============================================================
__global__ void build_kernels_kernel(const float* __restrict__ W_syn,   // [63][13][2]
                                     const float* __restrict__ W_obs)   // [63][25]
{
    int j = blockIdx.x * blockDim.x + threadIdx.x;

    // ---- synaptic cosine basis -> ek/ik ----
    if (j < TN) {
        double raw = 5.0 * log((double)j + 1.0 + 1e-8);
        float cb[NB];
        #pragma unroll
        for (int b = 0; b < NB; b++) {
            double phi = 0.5 * M_PI_D * (double)b;
            double v = 0.5 * cos(raw - phi) + 0.5;
            if (raw < phi - M_PI_D || raw > phi + M_PI_D) v = 0.0;
            cb[b] = (float)v;
        }
        for (int c = 0; c < CCH; c++) {
            float ae = 0.f, ai = 0.f;
            #pragma unroll
            for (int b = 0; b < NB; b++) {
                ae += W_syn[(c * NB + b) * 2 + 0] * cb[b];
                ai += W_syn[(c * NB + b) * 2 + 1] * cb[b];
            }
            g_ek[c * TN + j] = ae;
            g_ik[c * TN + j] = ai;
        }
    }

    // ---- observation basis -> ok ----
    if (j < OBS_LEN) {
        double xo = (double)(j - TN);
        double raw = 5.0 * log(fabs(xo) + 1.0 + 1e-8);
        float ob[NB];
        #pragma unroll
        for (int b = 0; b < NB; b++) {
            double phi = 0.5 * M_PI_D * (double)b;
            double v = 0.5 * cos(raw - phi) + 0.5;
            if (raw < phi - M_PI_D || raw > phi + M_PI_D) v = 0.0;
            ob[b] = (float)v;
        }
        for (int c = 0; c < CCH; c++) {
            // obs_basis row 0 = b0 everywhere; row 2i-1 nonzero for k>=TN; row 2i for k<=TN
            float a = W_obs[c * 25 + 0] * ob[0];
            #pragma unroll
            for (int b = 1; b < NB; b++) {
                if (j >= TN) a += W_obs[c * 25 + 2 * b - 1] * ob[b];
                if (j <= TN) a += W_obs[c * 25 + 2 * b    ] * ob[b];
            }
            g_ok[c * OBS_LEN + j] = a;
        }
    }
}

// ============================================================
// Kernel 1: SGEMM  outT[c][t] = sum_k A[t][k] * Csyn[c+1][k]
//   BM=128, BN=64 (63 valid + 1 zero pad col), BK=16, 256 thr
// ============================================================
#define BM 128
#define BN 64
#define BK 16

__global__ __launch_bounds__(256) void gemm_syn_kernel(
    const float* __restrict__ A,     // [TD][K]
    const float* __restrict__ Cs,    // [64][K] (row 0 skipped)
    float* __restrict__ outT,        // [CCH][TD]
    int K)
{
    __shared__ float sm[64 * 129 + 4];   // 33 KB, aliased: As/Bs in main loop, transpose buf in epilogue
    float (*As)[BM + 4] = reinterpret_cast<float(*)[BM + 4]>(sm);                 // 16 x 132
    float (*Bs)[BN + 4] = reinterpret_cast<float(*)[BN + 4]>(sm + BK * (BM + 4)); // 16 x 68

    const int tid  = threadIdx.x;
    const int tx   = tid & 15;          // 0..15 -> 4 cols each
    const int ty   = tid >> 4;          // 0..15 -> 8 rows each
    const int bm   = blockIdx.x * BM;
    const int lrow = tid >> 2;          // 0..63 loader row
    const int lq   = (tid & 3) << 2;    // 0,4,8,12 loader k-quad

    float acc[8][4];
    #pragma unroll
    for (int i = 0; i < 8; i++)
        #pragma unroll
        for (int j = 0; j < 4; j++) acc[i][j] = 0.f;

    for (int k0 = 0; k0 < K; k0 += BK) {
        // ---- A tile (with T and K-tail guards) ----
        #pragma unroll
        for (int h = 0; h < 2; h++) {
            int r = lrow + h * 64;
            int t = bm + r;
            float4 v = make_float4(0.f, 0.f, 0.f, 0.f);
            if (t < TD) {
                if (k0 + lq + 4 <= K) {
                    v = *reinterpret_cast<const float4*>(&A[(size_t)t * K + k0 + lq]);
                } else {
                    float tmp[4] = {0.f, 0.f, 0.f, 0.f};
                    for (int e = 0; e < 4; e++)
                        if (k0 + lq + e < K) tmp[e] = A[(size_t)t * K + k0 + lq + e];
                    v.x = tmp[0]; v.y = tmp[1]; v.z = tmp[2]; v.w = tmp[3];
                }
            }
            As[lq + 0][r] = v.x; As[lq + 1][r] = v.y;
            As[lq + 2][r] = v.z; As[lq + 3][r] = v.w;
        }
        // ---- B tile (row c uses Csyn[c+1]; c==63 is zero pad) ----
        {
            int c = lrow;
            float4 v = make_float4(0.f, 0.f, 0.f, 0.f);
            if (c < CCH) {
                size_t ro = (size_t)(c + 1) * K;
                if (k0 + lq + 4 <= K) {
                    v = *reinterpret_cast<const float4*>(&Cs[ro + k0 + lq]);
                } else {
                    float tmp[4] = {0.f, 0.f, 0.f, 0.f};
                    for (int e = 0; e < 4; e++)
                        if (k0 + lq + e < K) tmp[e] = Cs[ro + k0 + lq + e];
                    v.x = tmp[0]; v.y = tmp[1]; v.z = tmp[2]; v.w = tmp[3];
                }
            }
            Bs[lq + 0][c] = v.x; Bs[lq + 1][c] = v.y;
            Bs[lq + 2][c] = v.z; Bs[lq + 3][c] = v.w;
        }
        __syncthreads();

        #pragma unroll
        for (int kk = 0; kk < BK; kk++) {
            float a[8], b[4];
            *reinterpret_cast<float4*>(&a[0]) = *reinterpret_cast<const float4*>(&As[kk][ty * 8]);
            *reinterpret_cast<float4*>(&a[4]) = *reinterpret_cast<const float4*>(&As[kk][ty * 8 + 4]);
            *reinterpret_cast<float4*>(&b[0]) = *reinterpret_cast<const float4*>(&Bs[kk][tx * 4]);
            #pragma unroll
            for (int i = 0; i < 8; i++)
                #pragma unroll
                for (int j = 0; j < 4; j++)
                    acc[i][j] = fmaf(a[i], b[j], acc[i][j]);
        }
        __syncthreads();
    }

    // ---- transpose epilogue through smem -> coalesced [c][t] stores ----
    #pragma unroll
    for (int i = 0; i < 8; i++)
        #pragma unroll
        for (int j = 0; j < 4; j++)
            sm[(tx * 4 + j) * 129 + ty * 8 + i] = acc[i][j];
    __syncthreads();
    for (int idx = tid; idx < 64 * 128; idx += 256) {
        int c  = idx >> 7;
        int tl = idx & 127;
        int t  = bm + tl;
        if (c < CCH && t < TD)
            outT[(size_t)c * TD + t] = sm[c * 129 + tl];
    }
}

// ============================================================
// Kernel 2: temporal convs + Gumbel-softmax / sigmoid epilogue
//   block = (channel c, 2048-step time tile); 256 thr x 8 outputs
// ============================================================
#define TT 2048

__global__ __launch_bounds__(256) void conv_finish_kernel(
    const float* __restrict__ Z,      // [TD]
    const float* __restrict__ u,      // [TD][63][2]
    const float* __restrict__ Theta,  // [63]
    const float* __restrict__ temp_p, // scalar
    float* __restrict__ out)          // [2][TD][63]
{
    __shared__ float se_s[TT + TN + 8];       // 2256
    __shared__ float si_s[TT + TN + 8];
    __shared__ float z_s [TT + 2 * TN + 8];   // 2456
    __shared__ float ek_s[TN];
    __shared__ float ik_s[TN];
    __shared__ float ok_s[OBS_LEN + 3];

    const int c   = blockIdx.y;
    const int t0  = blockIdx.x * TT;
    const int tid = threadIdx.x;

    const float* se_g = g_syn_e + (size_t)c * TD;
    const float* si_g = g_syn_i + (size_t)c * TD;

    for (int i = tid; i < TT + TN - 1; i += 256) {          // window [t0-199, t0+TT)
        int t = t0 - (TN - 1) + i;
        float ve = 0.f, vi = 0.f;
        if (t >= 0 && t < TD) { ve = se_g[t]; vi = si_g[t]; }
        se_s[i] = ve; si_s[i] = vi;
    }
    for (int i = tid; i < TT + 2 * TN; i += 256) {          // window [t0-200, t0+TT+200)
        int t = t0 - TN + i;
        z_s[i] = (t >= 0 && t < TD) ? Z[t] : 0.f;
    }
    for (int j = tid; j < TN; j += 256) {
        ek_s[j] = g_ek[c * TN + j];
        ik_s[j] = g_ik[c * TN + j];
    }
    for (int j = tid; j < OBS_LEN; j += 256)
        ok_s[j] = g_ok[c * OBS_LEN + j];
    __syncthreads();

    const int tl0 = tid * 8;
    float acc[8];
    #pragma unroll
    for (int i = 0; i < 8; i++) acc[i] = 0.f;

    // ---- causal e/i convs: filt[t] = sum_j syn[t-j]*k[j], j in [0,200) ----
    // se_s index for (tl, j) is tl + 199 - j
    #pragma unroll 2
    for (int j0 = 0; j0 < TN; j0 += 4) {
        float4 we = *reinterpret_cast<const float4*>(&ek_s[j0]);
        float4 wi = *reinterpret_cast<const float4*>(&ik_s[j0]);
        int base = tl0 + (TN - 4) - j0;                      // tl0 + 196 - j0 (4-aligned, >=0)
        float s[12], q[12];
        *reinterpret_cast<float4*>(&s[0]) = *reinterpret_cast<const float4*>(&se_s[base]);
        *reinterpret_cast<float4*>(&s[4]) = *reinterpret_cast<const float4*>(&se_s[base + 4]);
        *reinterpret_cast<float4*>(&s[8]) = *reinterpret_cast<const float4*>(&se_s[base + 8]);
        *reinterpret_cast<float4*>(&q[0]) = *reinterpret_cast<const float4*>(&si_s[base]);
        *reinterpret_cast<float4*>(&q[4]) = *reinterpret_cast<const float4*>(&si_s[base + 4]);
        *reinterpret_cast<float4*>(&q[8]) = *reinterpret_cast<const float4*>(&si_s[base + 8]);
        const float wes[4] = {we.x, we.y, we.z, we.w};
        const float wis[4] = {wi.x, wi.y, wi.z, wi.w};
        #pragma unroll
        for (int dj = 0; dj < 4; dj++) {
            #pragma unroll
            for (int i = 0; i < 8; i++) {
                acc[i] = fmaf(s[i + 3 - dj], wes[dj], acc[i]);
                acc[i] = fmaf(q[i + 3 - dj], wis[dj], acc[i]);
            }
        }
    }

    // ---- obs conv: sum_j Z[t+200-j]*ok[j], j in [0,401) ----
    // z_s index for (tl, j) is tl + 400 - j
    #pragma unroll 2
    for (int j0 = 0; j0 < OBS_LEN - 1; j0 += 4) {
        float4 w = *reinterpret_cast<const float4*>(&ok_s[j0]);
        int base = tl0 + 396 - j0;                           // 4-aligned, >=0
        float s[12];
        *reinterpret_cast<float4*>(&s[0]) = *reinterpret_cast<const float4*>(&z_s[base]);
        *reinterpret_cast<float4*>(&s[4]) = *reinterpret_cast<const float4*>(&z_s[base + 4]);
        *reinterpret_cast<float4*>(&s[8]) = *reinterpret_cast<const float4*>(&z_s[base + 8]);
        const float ws[4] = {w.x, w.y, w.z, w.w};
        #pragma unroll
        for (int dj = 0; dj < 4; dj++) {
            #pragma unroll
            for (int i = 0; i < 8; i++)
                acc[i] = fmaf(s[i + 4 - dj], ws[dj], acc[i]);
        }
    }
    {   // tail tap j = 400 -> z_s[tl]
        float w = ok_s[OBS_LEN - 1];
        #pragma unroll
        for (int i = 0; i < 8; i++)
            acc[i] = fmaf(z_s[tl0 + i], w, acc[i]);
    }

    // ---- epilogue ----
    const float th   = Theta[c];
    const float temp = *temp_p;
    #pragma unroll
    for (int i = 0; i < 8; i++) {
        int t = t0 + tl0 + i;
        if (t < TD) {
            float L0 = acc[i] + th;
            const float* up = u + ((size_t)t * CCH + c) * 2;
            float g0 = -logf(-logf(up[0] + 1e-8f) + 1e-8f);
            float g1 = -logf(-logf(up[1] + 1e-8f) + 1e-8f);
            float zh = 1.f / (1.f + expf(-((L0 + g0 - g1) / temp)));
            float sg = 1.f / (1.f + expf(-L0));
            out[(size_t)t * CCH + c]                    = zh;   // Z_hid
            out[(size_t)TD * CCH + (size_t)t * CCH + c] = sg;   // sigmoid(L0)
        }
    }
}

// ============================================================
// launch
// ============================================================
extern "C" void kernel_launch(void* const* d_in, const int* in_sizes, int n_in,
                              void* d_out, int out_size)
{
    const float* S_e    = (const float*)d_in[0];   // [50000][2000]
    const float* S_i    = (const float*)d_in[1];   // [50000][500]
    const float* Z_obs  = (const float*)d_in[2];   // [50000]
    const float* temp   = (const float*)d_in[3];   // scalar
    const float* u      = (const float*)d_in[4];   // [50000][63][2]
    const float* C_se   = (const float*)d_in[5];   // [64][2000]
    const float* C_si   = (const float*)d_in[6];   // [64][500]
    const float* W_syn  = (const float*)d_in[7];   // [63][13][2]
    const float* W_obs  = (const float*)d_in[8];   // [63][25]
    const float* Theta  = (const float*)d_in[9];   // [63]
    float* out = (float*)d_out;

    (void)in_sizes; (void)n_in; (void)out_size;

    float* syn_e_ptr; float* syn_i_ptr;
    cudaGetSymbolAddress((void**)&syn_e_ptr, g_syn_e);
    cudaGetSymbolAddress((void**)&syn_i_ptr, g_syn_i);

    build_kernels_kernel<<<2, 256>>>(W_syn, W_obs);

    int grid_m = (TD + BM - 1) / BM;   // 391
    gemm_syn_kernel<<<grid_m, 256>>>(S_e, C_se, syn_e_ptr, E_NO);
    gemm_syn_kernel<<<grid_m, 256>>>(S_i, C_si, syn_i_ptr, I_NO);

    dim3 cg((TD + TT - 1) / TT, CCH);  // 25 x 63
    conv_finish_kernel<<<cg, 256>>>(Z_obs, u, Theta, temp, out);
}

// round 5
// speedup vs baseline: 1.8192x; 1.8192x over previous
#include <cuda_runtime.h>
#include <cstdint>
#include <math.h>

// ---------------- problem constants ----------------
#define TD      50000
#define E_NO    2000
#define I_NO    500
#define CCH     63
#define TN      200
#define OBS_LEN 401
#define NB      13
#define M_PI_D  3.14159265358979323846

// ---------------- device scratch ----------------
__device__ float g_ek[CCH * TN];
__device__ float g_ik[CCH * TN];
__device__ float g_ok[CCH * (OBS_LEN + 3)];
__device__ float g_syn_e[CCH * TD];
__device__ float g_syn_i[CCH * TD];

__device__ __forceinline__ uint32_t tf32u(uint32_t xu) {
    float y;
    asm("cvt.rna.tf32.f32 %0, %1;" : "=f"(y) : "f"(__uint_as_float(xu)));
    return __float_as_uint(y);
}

__device__ __forceinline__ uint32_t smem_u32(const void* p) {
    uint32_t a;
    asm("{ .reg .u64 t; cvta.to.shared.u64 t, %1; cvt.u32.u64 %0, t; }" : "=r"(a) : "l"(p));
    return a;
}
__device__ __forceinline__ void cp_async16(uint32_t dst, const void* src, bool pred) {
    asm volatile(
        "{\n\t.reg .pred p;\n\t"
        "setp.ne.b32 p, %2, 0;\n\t"
        "@p cp.async.ca.shared.global [%0], [%1], 16;\n\t"
        "@!p st.shared.v4.b32 [%0], {%3,%3,%3,%3};\n\t}"
        :: "r"(dst), "l"(src), "r"((int)pred), "r"(0u) : "memory");
}
#define CP_COMMIT() asm volatile("cp.async.commit_group;" ::: "memory")
#define CP_WAIT1()  asm volatile("cp.async.wait_group 1;" ::: "memory")
#define CP_WAIT0()  asm volatile("cp.async.wait_group 0;" ::: "memory")

// ============================================================
// Kernel 0: build temporal kernels from bases (double, as numpy)
// ============================================================
__global__ void build_kernels_kernel(const float* __restrict__ W_syn,   // [63][13][2]
                                     const float* __restrict__ W_obs)   // [63][25]
{
    int j = blockIdx.x * blockDim.x + threadIdx.x;

    if (j < TN) {
        double raw = 5.0 * log((double)j + 1.0 + 1e-8);
        float cb[NB];
        #pragma unroll
        for (int b = 0; b < NB; b++) {
            double phi = 0.5 * M_PI_D * (double)b;
            double v = 0.5 * cos(raw - phi) + 0.5;
            if (raw < phi - M_PI_D || raw > phi + M_PI_D) v = 0.0;
            cb[b] = (float)v;
        }
        for (int c = 0; c < CCH; c++) {
            float ae = 0.f, ai = 0.f;
            #pragma unroll
            for (int b = 0; b < NB; b++) {
                ae += W_syn[(c * NB + b) * 2 + 0] * cb[b];
                ai += W_syn[(c * NB + b) * 2 + 1] * cb[b];
            }
            g_ek[c * TN + j] = ae;
            g_ik[c * TN + j] = ai;
        }
    }

    if (j < OBS_LEN) {
        double xo = (double)(j - TN);
        double raw = 5.0 * log(fabs(xo) + 1.0 + 1e-8);
        float ob[NB];
        #pragma unroll
        for (int b = 0; b < NB; b++) {
            double phi = 0.5 * M_PI_D * (double)b;
            double v = 0.5 * cos(raw - phi) + 0.5;
            if (raw < phi - M_PI_D || raw > phi + M_PI_D) v = 0.0;
            ob[b] = (float)v;
        }
        for (int c = 0; c < CCH; c++) {
            float a = W_obs[c * 25 + 0] * ob[0];
            #pragma unroll
            for (int b = 1; b < NB; b++) {
                if (j >= TN) a += W_obs[c * 25 + 2 * b - 1] * ob[b];
                if (j <= TN) a += W_obs[c * 25 + 2 * b    ] * ob[b];
            }
            g_ok[c * (OBS_LEN + 3) + j] = a;
        }
    }
}

// ============================================================
// Kernel 1: tf32 mma.sync GEMM  outT[c][t] = sum_k A[t][k]*Cs[c+1][k]
//   BM=128, BN=64, BK=32; 8 warps as 4(M) x 2(N), warp tile 32x32
//   cp.async double-buffered; fp32 staged in smem, cvt->tf32 at LDS
// ============================================================
#define GBM  128
#define GBK  32
#define APITCH 36                         // 32 + 4 pad floats
#define AS_F (128 * APITCH)
#define BS_F (64 * APITCH)
#define STAGE_F (AS_F + BS_F)             // 6912 floats
#define GSMEM_BYTES (2 * STAGE_F * 4)     // 55296 B

__global__ __launch_bounds__(256) void gemm_mma_kernel(
    const float* __restrict__ A,     // [TD][K]
    const float* __restrict__ Cs,    // [64][K] (row 0 skipped)
    float* __restrict__ outT,        // [CCH][TD]
    int K, int S)
{
    extern __shared__ float smf[];
    uint32_t* smu = reinterpret_cast<uint32_t*>(smf);
    const uint32_t sbase = smem_u32(smf);

    const int tid  = threadIdx.x;
    const int wid  = tid >> 5;
    const int lane = tid & 31;
    const int g    = lane >> 2;          // 0..7
    const int t4   = lane & 3;           // 0..3
    const int wm   = (wid & 3) * 32;
    const int wn   = (wid >> 2) * 32;
    const int bm   = blockIdx.x * GBM;

    float acc[2][4][4];
    #pragma unroll
    for (int mi = 0; mi < 2; mi++)
        #pragma unroll
        for (int ni = 0; ni < 4; ni++)
            #pragma unroll
            for (int r = 0; r < 4; r++) acc[mi][ni][r] = 0.f;

    // loader mapping: idx -> row = idx>>3, quad = idx&7 (16B each)
    auto load_stage = [&](int s, int buf) {
        const int k0 = s * GBK;
        const uint32_t ab = sbase + (uint32_t)(buf * STAGE_F) * 4u;
        const uint32_t bb = ab + (uint32_t)AS_F * 4u;
        #pragma unroll
        for (int j = 0; j < 4; j++) {
            int idx = tid + 256 * j, r = idx >> 3, c4 = idx & 7, k = k0 + c4 * 4;
            bool ok = (bm + r < TD) && (k + 4 <= K);
            cp_async16(ab + (uint32_t)(r * APITCH + c4 * 4) * 4u,
                       A + (size_t)(bm + r) * K + k, ok);
        }
        #pragma unroll
        for (int j = 0; j < 2; j++) {
            int idx = tid + 256 * j, r = idx >> 3, c4 = idx & 7, k = k0 + c4 * 4;
            bool ok = (r < CCH) && (k + 4 <= K);
            cp_async16(bb + (uint32_t)(r * APITCH + c4 * 4) * 4u,
                       Cs + (size_t)(r + 1) * K + k, ok);
        }
        CP_COMMIT();
    };

    auto compute = [&](int buf) {
        const uint32_t* As = smu + buf * STAGE_F;
        const uint32_t* Bs = As + AS_F;
        #pragma unroll
        for (int kk = 0; kk < 4; kk++) {
            const int k0 = kk * 8;
            uint32_t af[2][4];
            #pragma unroll
            for (int mi = 0; mi < 2; mi++) {
                int r = wm + mi * 16 + g;
                af[mi][0] = tf32u(As[(r)     * APITCH + k0 + t4]);
                af[mi][1] = tf32u(As[(r + 8) * APITCH + k0 + t4]);
                af[mi][2] = tf32u(As[(r)     * APITCH + k0 + 4 + t4]);
                af[mi][3] = tf32u(As[(r + 8) * APITCH + k0 + 4 + t4]);
            }
            uint32_t bf[4][2];
            #pragma unroll
            for (int ni = 0; ni < 4; ni++) {
                int cb = wn + ni * 8 + g;
                bf[ni][0] = tf32u(Bs[cb * APITCH + k0 + t4]);
                bf[ni][1] = tf32u(Bs[cb * APITCH + k0 + 4 + t4]);
            }
            #pragma unroll
            for (int mi = 0; mi < 2; mi++)
                #pragma unroll
                for (int ni = 0; ni < 4; ni++) {
                    asm volatile(
                        "mma.sync.aligned.m16n8k8.row.col.f32.tf32.tf32.f32 "
                        "{%0,%1,%2,%3}, {%4,%5,%6,%7}, {%8,%9}, {%0,%1,%2,%3};"
                        : "+f"(acc[mi][ni][0]), "+f"(acc[mi][ni][1]),
                          "+f"(acc[mi][ni][2]), "+f"(acc[mi][ni][3])
                        : "r"(af[mi][0]), "r"(af[mi][1]), "r"(af[mi][2]), "r"(af[mi][3]),
                          "r"(bf[ni][0]), "r"(bf[ni][1]));
                }
        }
    };

    // ---- software pipeline: prefetch depth 2 ----
    load_stage(0, 0);
    if (S > 1) load_stage(1, 1);

    for (int s = 0; s < S; s++) {
        if (s + 2 < S) {
            CP_WAIT1();            // stage s resident (s+1 may be in flight)
        } else {
            CP_WAIT0();
        }
        __syncthreads();
        compute(s & 1);
        __syncthreads();
        if (s + 2 < S) load_stage(s + 2, s & 1);
    }

    // ---- transpose epilogue through smem -> coalesced [c][t] stores ----
    #pragma unroll
    for (int mi = 0; mi < 2; mi++)
        #pragma unroll
        for (int ni = 0; ni < 4; ni++) {
            int n0 = wn + ni * 8 + 2 * t4;
            int m0 = wm + mi * 16 + g;
            smf[(n0)     * 132 + m0]     = acc[mi][ni][0];
            smf[(n0 + 1) * 132 + m0]     = acc[mi][ni][1];
            smf[(n0)     * 132 + m0 + 8] = acc[mi][ni][2];
            smf[(n0 + 1) * 132 + m0 + 8] = acc[mi][ni][3];
        }
    __syncthreads();
    for (int idx = tid; idx < 64 * 128; idx += 256) {
        int c  = idx >> 7;
        int tl = idx & 127;
        int t  = bm + tl;
        if (c < CCH && t < TD)
            outT[(size_t)c * TD + t] = smf[c * 132 + tl];
    }
}

// ============================================================
// Kernel 2: temporal convs + Gumbel-softmax / sigmoid epilogue
//   sliding register windows: 1 float4 LDS per array per 4 taps
// ============================================================
#define TT 2048

__global__ __launch_bounds__(256) void conv_finish_kernel(
    const float* __restrict__ Z,
    const float* __restrict__ u,
    const float* __restrict__ Theta,
    const float* __restrict__ temp_p,
    float* __restrict__ out)
{
    __shared__ __align__(16) float se_s[TT + TN + 16];
    __shared__ __align__(16) float si_s[TT + TN + 16];
    __shared__ __align__(16) float z_s [TT + 2 * TN + 16];
    __shared__ __align__(16) float ek_s[TN];
    __shared__ __align__(16) float ik_s[TN];
    __shared__ __align__(16) float ok_s[OBS_LEN + 3];

    const int c   = blockIdx.x;        // channel fastest
    const int t0  = blockIdx.y * TT;
    const int tid = threadIdx.x;

    const float* se_g = g_syn_e + (size_t)c * TD;
    const float* si_g = g_syn_i + (size_t)c * TD;

    for (int i = tid; i < TT + TN + 16; i += 256) {
        int t = t0 - (TN - 1) + i;
        float ve = 0.f, vi = 0.f;
        if (t >= 0 && t < TD) { ve = se_g[t]; vi = si_g[t]; }
        se_s[i] = ve; si_s[i] = vi;
    }
    for (int i = tid; i < TT + 2 * TN + 16; i += 256) {
        int t = t0 - TN + i;
        z_s[i] = (t >= 0 && t < TD) ? Z[t] : 0.f;
    }
    for (int j = tid; j < TN; j += 256) {
        ek_s[j] = g_ek[c * TN + j];
        ik_s[j] = g_ik[c * TN + j];
    }
    for (int j = tid; j < OBS_LEN; j += 256)
        ok_s[j] = g_ok[c * (OBS_LEN + 3) + j];
    __syncthreads();

    const int tl0 = tid * 8;
    float acc[8];
    #pragma unroll
    for (int i = 0; i < 8; i++) acc[i] = 0.f;

    // ---------- causal e/i convs (sliding register window) ----------
    {
        float ew[12], iw[12];
        #pragma unroll
        for (int x = 0; x < 3; x++) {
            float4 a = *reinterpret_cast<const float4*>(&se_s[tl0 + 4 * x]);
            float4 b = *reinterpret_cast<const float4*>(&si_s[tl0 + 4 * x]);
            ew[4 * x] = a.x; ew[4 * x + 1] = a.y; ew[4 * x + 2] = a.z; ew[4 * x + 3] = a.w;
            iw[4 * x] = b.x; iw[4 * x + 1] = b.y; iw[4 * x + 2] = b.z; iw[4 * x + 3] = b.w;
        }
        #pragma unroll 5
        for (int p = 0; p < 50; p++) {
            float4 we4 = *reinterpret_cast<const float4*>(&ek_s[196 - 4 * p]);
            float4 wi4 = *reinterpret_cast<const float4*>(&ik_s[196 - 4 * p]);
            float4 ne  = *reinterpret_cast<const float4*>(&se_s[tl0 + 12 + 4 * p]);
            float4 ni  = *reinterpret_cast<const float4*>(&si_s[tl0 + 12 + 4 * p]);
            const float we[4] = {we4.x, we4.y, we4.z, we4.w};
            const float wi[4] = {wi4.x, wi4.y, wi4.z, wi4.w};
            #pragma unroll
            for (int dj = 0; dj < 4; dj++) {
                #pragma unroll
                for (int i = 0; i < 8; i++) {
                    acc[i] = fmaf(ew[i + 3 - dj], we[dj], acc[i]);
                    acc[i] = fmaf(iw[i + 3 - dj], wi[dj], acc[i]);
                }
            }
            #pragma unroll
            for (int x = 0; x < 8; x++) { ew[x] = ew[x + 4]; iw[x] = iw[x + 4]; }
            ew[8] = ne.x; ew[9] = ne.y; ew[10] = ne.z; ew[11] = ne.w;
            iw[8] = ni.x; iw[9] = ni.y; iw[10] = ni.z; iw[11] = ni.w;
        }
    }

    // ---------- obs conv ----------
    {
        float zw[12];
        #pragma unroll
        for (int x = 0; x < 3; x++) {
            float4 a = *reinterpret_cast<const float4*>(&z_s[tl0 + 4 * x]);
            zw[4 * x] = a.x; zw[4 * x + 1] = a.y; zw[4 * x + 2] = a.z; zw[4 * x + 3] = a.w;
        }
        {   // tail tap j = 400 -> z index tl0 + i
            float w = ok_s[400];
            #pragma unroll
            for (int i = 0; i < 8; i++) acc[i] = fmaf(zw[i], w, acc[i]);
        }
        #pragma unroll 5
        for (int p = 0; p < 100; p++) {
            float4 w4 = *reinterpret_cast<const float4*>(&ok_s[396 - 4 * p]);
            float4 nz = *reinterpret_cast<const float4*>(&z_s[tl0 + 12 + 4 * p]);
            const float w[4] = {w4.x, w4.y, w4.z, w4.w};
            #pragma unroll
            for (int dj = 0; dj < 4; dj++) {
                #pragma unroll
                for (int i = 0; i < 8; i++)
                    acc[i] = fmaf(zw[i + 4 - dj], w[dj], acc[i]);
            }
            #pragma unroll
            for (int x = 0; x < 8; x++) zw[x] = zw[x + 4];
            zw[8] = nz.x; zw[9] = nz.y; zw[10] = nz.z; zw[11] = nz.w;
        }
    }

    // ---------- epilogue ----------
    const float th   = Theta[c];
    const float temp = *temp_p;
    #pragma unroll
    for (int i = 0; i < 8; i++) {
        int t = t0 + tl0 + i;
        if (t < TD) {
            float L0 = acc[i] + th;
            float2 uv = *reinterpret_cast<const float2*>(&u[((size_t)t * CCH + c) * 2]);
            float g0 = -logf(-logf(uv.x + 1e-8f) + 1e-8f);
            float g1 = -logf(-logf(uv.y + 1e-8f) + 1e-8f);
            float zh = 1.f / (1.f + expf(-((L0 + g0 - g1) / temp)));
            float sg = 1.f / (1.f + expf(-L0));
            out[(size_t)t * CCH + c]                    = zh;
            out[(size_t)TD * CCH + (size_t)t * CCH + c] = sg;
        }
    }
}

// ============================================================
// launch
// ============================================================
extern "C" void kernel_launch(void* const* d_in, const int* in_sizes, int n_in,
                              void* d_out, int out_size)
{
    const float* S_e    = (const float*)d_in[0];
    const float* S_i    = (const float*)d_in[1];
    const float* Z_obs  = (const float*)d_in[2];
    const float* temp   = (const float*)d_in[3];
    const float* u      = (const float*)d_in[4];
    const float* C_se   = (const float*)d_in[5];
    const float* C_si   = (const float*)d_in[6];
    const float* W_syn  = (const float*)d_in[7];
    const float* W_obs  = (const float*)d_in[8];
    const float* Theta  = (const float*)d_in[9];
    float* out = (float*)d_out;
    (void)in_sizes; (void)n_in; (void)out_size;

    cudaFuncSetAttribute(gemm_mma_kernel, cudaFuncAttributeMaxDynamicSharedMemorySize, GSMEM_BYTES);

    float* syn_e_ptr; float* syn_i_ptr;
    cudaGetSymbolAddress((void**)&syn_e_ptr, g_syn_e);
    cudaGetSymbolAddress((void**)&syn_i_ptr, g_syn_i);

    build_kernels_kernel<<<2, 256>>>(W_syn, W_obs);

    const int grid_m = (TD + GBM - 1) / GBM;   // 391
    gemm_mma_kernel<<<grid_m, 256, GSMEM_BYTES>>>(S_e, C_se, syn_e_ptr, E_NO, (E_NO + GBK - 1) / GBK);
    gemm_mma_kernel<<<grid_m, 256, GSMEM_BYTES>>>(S_i, C_si, syn_i_ptr, I_NO, (I_NO + GBK - 1) / GBK);

    dim3 cg(CCH, (TD + TT - 1) / TT);          // 63 x 25
    conv_finish_kernel<<<cg, 256>>>(Z_obs, u, Theta, temp, out);
}

// round 6
// speedup vs baseline: 2.1611x; 1.1880x over previous
#include <cuda_runtime.h>
#include <cstdint>
#include <math.h>

// ---------------- problem constants ----------------
#define TD      50000
#define E_NO    2000
#define I_NO    500
#define CCH     63
#define TN      200
#define OBS_LEN 401
#define NB      13
#define M_PI_D  3.14159265358979323846

// ---------------- device scratch ----------------
__device__ float g_ek[CCH * TN];
__device__ float g_ik[CCH * TN];
__device__ float g_ok[CCH * (OBS_LEN + 3)];
__device__ float g_syn_e[CCH * TD];
__device__ float g_syn_i[CCH * TD];

// pack two fp32 -> bf16x2 (lo = first, hi = second)
__device__ __forceinline__ uint32_t bf2(float lo, float hi) {
    uint32_t r;
    asm("cvt.rn.bf16x2.f32 %0, %1, %2;" : "=r"(r) : "f"(hi), "f"(lo));
    return r;
}

// ============================================================
// Kernel 0: build temporal kernels from bases (double, as numpy)
// ============================================================
__global__ void build_kernels_kernel(const float* __restrict__ W_syn,   // [63][13][2]
                                     const float* __restrict__ W_obs)   // [63][25]
{
    int j = blockIdx.x * blockDim.x + threadIdx.x;

    if (j < TN) {
        double raw = 5.0 * log((double)j + 1.0 + 1e-8);
        float cb[NB];
        #pragma unroll
        for (int b = 0; b < NB; b++) {
            double phi = 0.5 * M_PI_D * (double)b;
            double v = 0.5 * cos(raw - phi) + 0.5;
            if (raw < phi - M_PI_D || raw > phi + M_PI_D) v = 0.0;
            cb[b] = (float)v;
        }
        for (int c = 0; c < CCH; c++) {
            float ae = 0.f, ai = 0.f;
            #pragma unroll
            for (int b = 0; b < NB; b++) {
                ae += W_syn[(c * NB + b) * 2 + 0] * cb[b];
                ai += W_syn[(c * NB + b) * 2 + 1] * cb[b];
            }
            g_ek[c * TN + j] = ae;
            g_ik[c * TN + j] = ai;
        }
    }

    if (j < OBS_LEN) {
        double xo = (double)(j - TN);
        double raw = 5.0 * log(fabs(xo) + 1.0 + 1e-8);
        float ob[NB];
        #pragma unroll
        for (int b = 0; b < NB; b++) {
            double phi = 0.5 * M_PI_D * (double)b;
            double v = 0.5 * cos(raw - phi) + 0.5;
            if (raw < phi - M_PI_D || raw > phi + M_PI_D) v = 0.0;
            ob[b] = (float)v;
        }
        for (int c = 0; c < CCH; c++) {
            float a = W_obs[c * 25 + 0] * ob[0];
            #pragma unroll
            for (int b = 1; b < NB; b++) {
                if (j >= TN) a += W_obs[c * 25 + 2 * b - 1] * ob[b];
                if (j <= TN) a += W_obs[c * 25 + 2 * b    ] * ob[b];
            }
            g_ok[c * (OBS_LEN + 3) + j] = a;
        }
    }
}

// ============================================================
// Kernel 1: bf16 mma.sync GEMM  outT[c][t] = sum_k A[t][k]*Cs[c+1][k]
//   BM=128, BN=64, BK=32 floats; 8 warps 4(M)x2(N), warp tile 32x32
//   m16n8k16 bf16; fp32 LDG -> cvt.bf16x2 -> STS, reg double buffer
//   blockIdx.y selects the E (y=0) or I (y=1) problem
// ============================================================
#define GBM     128
#define GBK     32
#define APW     20                        // smem row pitch in 32-bit words (80B)
#define AW      (128 * APW)               // A stage words
#define BW      (64 * APW)                // B stage words
#define STW     (AW + BW)                 // 3840 words / stage
#define GSMEM_BYTES (64 * 132 * 4)        // 33792 B (> 2*STW*4 = 30720)

__global__ __launch_bounds__(256) void gemm_bf16_kernel(
    const float* __restrict__ Ae, const float* __restrict__ Cse, float* __restrict__ oute,
    const float* __restrict__ Ai, const float* __restrict__ Csi, float* __restrict__ outi)
{
    extern __shared__ float smf[];
    uint32_t* smw = reinterpret_cast<uint32_t*>(smf);

    const float* A; const float* Cs; float* outT; int K;
    if (blockIdx.y == 0) { A = Ae; Cs = Cse; outT = oute; K = E_NO; }
    else                 { A = Ai; Cs = Csi; outT = outi; K = I_NO; }
    const int S = (K + GBK - 1) / GBK;

    const int tid  = threadIdx.x;
    const int wid  = tid >> 5;
    const int lane = tid & 31;
    const int g    = lane >> 2;
    const int t4   = lane & 3;
    const int wm   = (wid & 3) * 32;
    const int wn   = (wid >> 2) * 32;
    const int bm   = blockIdx.x * GBM;

    float acc[2][4][4];
    #pragma unroll
    for (int mi = 0; mi < 2; mi++)
        #pragma unroll
        for (int ni = 0; ni < 4; ni++)
            #pragma unroll
            for (int r = 0; r < 4; r++) acc[mi][ni][r] = 0.f;

    float4 ra[4], rb[2];

    // A: 1024 float4 / stage -> 4 per thread; B: 512 -> 2 per thread
    auto ldg_stage = [&](int s) {
        const int k0 = s * GBK;
        #pragma unroll
        for (int j = 0; j < 4; j++) {
            int idx = tid + 256 * j, r = idx >> 3, q = idx & 7, k = k0 + q * 4;
            float4 v = make_float4(0.f, 0.f, 0.f, 0.f);
            if ((bm + r < TD) && (k + 4 <= K))
                v = *reinterpret_cast<const float4*>(A + (size_t)(bm + r) * K + k);
            ra[j] = v;
        }
        #pragma unroll
        for (int j = 0; j < 2; j++) {
            int idx = tid + 256 * j, r = idx >> 3, q = idx & 7, k = k0 + q * 4;
            float4 v = make_float4(0.f, 0.f, 0.f, 0.f);
            if ((r < CCH) && (k + 4 <= K))
                v = *reinterpret_cast<const float4*>(Cs + (size_t)(r + 1) * K + k);
            rb[j] = v;
        }
    };
    auto sts_stage = [&](int buf) {
        uint32_t* ab = smw + buf * STW;
        uint32_t* bb = ab + AW;
        #pragma unroll
        for (int j = 0; j < 4; j++) {
            int idx = tid + 256 * j, r = idx >> 3, q = idx & 7;
            uint2* p = reinterpret_cast<uint2*>(ab + r * APW + q * 2);
            *p = make_uint2(bf2(ra[j].x, ra[j].y), bf2(ra[j].z, ra[j].w));
        }
        #pragma unroll
        for (int j = 0; j < 2; j++) {
            int idx = tid + 256 * j, r = idx >> 3, q = idx & 7;
            uint2* p = reinterpret_cast<uint2*>(bb + r * APW + q * 2);
            *p = make_uint2(bf2(rb[j].x, rb[j].y), bf2(rb[j].z, rb[j].w));
        }
    };
    auto compute = [&](int buf) {
        const uint32_t* As = smw + buf * STW;
        const uint32_t* Bs = As + AW;
        #pragma unroll
        for (int ks = 0; ks < 2; ks++) {            // two k16 steps per stage
            const int kw = ks * 8;                  // word offset
            uint32_t af[2][4];
            #pragma unroll
            for (int mi = 0; mi < 2; mi++) {
                int r = wm + mi * 16 + g;
                af[mi][0] = As[(r)     * APW + kw + t4];
                af[mi][1] = As[(r + 8) * APW + kw + t4];
                af[mi][2] = As[(r)     * APW + kw + 4 + t4];
                af[mi][3] = As[(r + 8) * APW + kw + 4 + t4];
            }
            uint32_t bf[4][2];
            #pragma unroll
            for (int ni = 0; ni < 4; ni++) {
                int n = wn + ni * 8 + g;
                bf[ni][0] = Bs[n * APW + kw + t4];
                bf[ni][1] = Bs[n * APW + kw + 4 + t4];
            }
            #pragma unroll
            for (int mi = 0; mi < 2; mi++)
                #pragma unroll
                for (int ni = 0; ni < 4; ni++) {
                    asm volatile(
                        "mma.sync.aligned.m16n8k16.row.col.f32.bf16.bf16.f32 "
                        "{%0,%1,%2,%3}, {%4,%5,%6,%7}, {%8,%9}, {%0,%1,%2,%3};"
                        : "+f"(acc[mi][ni][0]), "+f"(acc[mi][ni][1]),
                          "+f"(acc[mi][ni][2]), "+f"(acc[mi][ni][3])
                        : "r"(af[mi][0]), "r"(af[mi][1]), "r"(af[mi][2]), "r"(af[mi][3]),
                          "r"(bf[ni][0]), "r"(bf[ni][1]));
                }
        }
    };

    // ---- register double-buffered pipeline ----
    ldg_stage(0);
    sts_stage(0);
    __syncthreads();

    for (int s = 0; s < S; s++) {
        const bool have_next = (s + 1 < S);
        if (have_next) ldg_stage(s + 1);
        compute(s & 1);
        __syncthreads();
        if (have_next) {
            sts_stage((s + 1) & 1);
            __syncthreads();
        }
    }

    // ---- transpose epilogue through smem -> coalesced [c][t] stores ----
    #pragma unroll
    for (int mi = 0; mi < 2; mi++)
        #pragma unroll
        for (int ni = 0; ni < 4; ni++) {
            int n0 = wn + ni * 8 + 2 * t4;
            int m0 = wm + mi * 16 + g;
            smf[(n0)     * 132 + m0]     = acc[mi][ni][0];
            smf[(n0 + 1) * 132 + m0]     = acc[mi][ni][1];
            smf[(n0)     * 132 + m0 + 8] = acc[mi][ni][2];
            smf[(n0 + 1) * 132 + m0 + 8] = acc[mi][ni][3];
        }
    __syncthreads();
    for (int idx = tid; idx < 64 * 128; idx += 256) {
        int c  = idx >> 7;
        int tl = idx & 127;
        int t  = bm + tl;
        if (c < CCH && t < TD)
            outT[(size_t)c * TD + t] = smf[c * 132 + tl];
    }
}

// ============================================================
// Kernel 2: temporal convs + Gumbel-softmax / sigmoid epilogue
//   sliding register windows: 1 float4 LDS per array per 4 taps
// ============================================================
#define TT 2048

__global__ __launch_bounds__(256) void conv_finish_kernel(
    const float* __restrict__ Z,
    const float* __restrict__ u,
    const float* __restrict__ Theta,
    const float* __restrict__ temp_p,
    float* __restrict__ out)
{
    __shared__ __align__(16) float se_s[TT + TN + 16];
    __shared__ __align__(16) float si_s[TT + TN + 16];
    __shared__ __align__(16) float z_s [TT + 2 * TN + 16];
    __shared__ __align__(16) float ek_s[TN];
    __shared__ __align__(16) float ik_s[TN];
    __shared__ __align__(16) float ok_s[OBS_LEN + 3];

    const int c   = blockIdx.x;        // channel fastest
    const int t0  = blockIdx.y * TT;
    const int tid = threadIdx.x;

    const float* se_g = g_syn_e + (size_t)c * TD;
    const float* si_g = g_syn_i + (size_t)c * TD;

    for (int i = tid; i < TT + TN + 16; i += 256) {
        int t = t0 - (TN - 1) + i;
        float ve = 0.f, vi = 0.f;
        if (t >= 0 && t < TD) { ve = se_g[t]; vi = si_g[t]; }
        se_s[i] = ve; si_s[i] = vi;
    }
    for (int i = tid; i < TT + 2 * TN + 16; i += 256) {
        int t = t0 - TN + i;
        z_s[i] = (t >= 0 && t < TD) ? Z[t] : 0.f;
    }
    for (int j = tid; j < TN; j += 256) {
        ek_s[j] = g_ek[c * TN + j];
        ik_s[j] = g_ik[c * TN + j];
    }
    for (int j = tid; j < OBS_LEN; j += 256)
        ok_s[j] = g_ok[c * (OBS_LEN + 3) + j];
    __syncthreads();

    const int tl0 = tid * 8;
    float acc[8];
    #pragma unroll
    for (int i = 0; i < 8; i++) acc[i] = 0.f;

    // ---------- causal e/i convs (sliding register window) ----------
    {
        float ew[12], iw[12];
        #pragma unroll
        for (int x = 0; x < 3; x++) {
            float4 a = *reinterpret_cast<const float4*>(&se_s[tl0 + 4 * x]);
            float4 b = *reinterpret_cast<const float4*>(&si_s[tl0 + 4 * x]);
            ew[4 * x] = a.x; ew[4 * x + 1] = a.y; ew[4 * x + 2] = a.z; ew[4 * x + 3] = a.w;
            iw[4 * x] = b.x; iw[4 * x + 1] = b.y; iw[4 * x + 2] = b.z; iw[4 * x + 3] = b.w;
        }
        #pragma unroll 5
        for (int p = 0; p < 50; p++) {
            float4 we4 = *reinterpret_cast<const float4*>(&ek_s[196 - 4 * p]);
            float4 wi4 = *reinterpret_cast<const float4*>(&ik_s[196 - 4 * p]);
            float4 ne  = *reinterpret_cast<const float4*>(&se_s[tl0 + 12 + 4 * p]);
            float4 ni  = *reinterpret_cast<const float4*>(&si_s[tl0 + 12 + 4 * p]);
            const float we[4] = {we4.x, we4.y, we4.z, we4.w};
            const float wi[4] = {wi4.x, wi4.y, wi4.z, wi4.w};
            #pragma unroll
            for (int dj = 0; dj < 4; dj++) {
                #pragma unroll
                for (int i = 0; i < 8; i++) {
                    acc[i] = fmaf(ew[i + 3 - dj], we[dj], acc[i]);
                    acc[i] = fmaf(iw[i + 3 - dj], wi[dj], acc[i]);
                }
            }
            #pragma unroll
            for (int x = 0; x < 8; x++) { ew[x] = ew[x + 4]; iw[x] = iw[x + 4]; }
            ew[8] = ne.x; ew[9] = ne.y; ew[10] = ne.z; ew[11] = ne.w;
            iw[8] = ni.x; iw[9] = ni.y; iw[10] = ni.z; iw[11] = ni.w;
        }
    }

    // ---------- obs conv ----------
    {
        float zw[12];
        #pragma unroll
        for (int x = 0; x < 3; x++) {
            float4 a = *reinterpret_cast<const float4*>(&z_s[tl0 + 4 * x]);
            zw[4 * x] = a.x; zw[4 * x + 1] = a.y; zw[4 * x + 2] = a.z; zw[4 * x + 3] = a.w;
        }
        {   // tail tap j = 400 -> z index tl0 + i
            float w = ok_s[400];
            #pragma unroll
            for (int i = 0; i < 8; i++) acc[i] = fmaf(zw[i], w, acc[i]);
        }
        #pragma unroll 5
        for (int p = 0; p < 100; p++) {
            float4 w4 = *reinterpret_cast<const float4*>(&ok_s[396 - 4 * p]);
            float4 nz = *reinterpret_cast<const float4*>(&z_s[tl0 + 12 + 4 * p]);
            const float w[4] = {w4.x, w4.y, w4.z, w4.w};
            #pragma unroll
            for (int dj = 0; dj < 4; dj++) {
                #pragma unroll
                for (int i = 0; i < 8; i++)
                    acc[i] = fmaf(zw[i + 4 - dj], w[dj], acc[i]);
            }
            #pragma unroll
            for (int x = 0; x < 8; x++) zw[x] = zw[x + 4];
            zw[8] = nz.x; zw[9] = nz.y; zw[10] = nz.z; zw[11] = nz.w;
        }
    }

    // ---------- epilogue ----------
    const float th   = Theta[c];
    const float temp = *temp_p;
    #pragma unroll
    for (int i = 0; i < 8; i++) {
        int t = t0 + tl0 + i;
        if (t < TD) {
            float L0 = acc[i] + th;
            float2 uv = *reinterpret_cast<const float2*>(&u[((size_t)t * CCH + c) * 2]);
            float g0 = -logf(-logf(uv.x + 1e-8f) + 1e-8f);
            float g1 = -logf(-logf(uv.y + 1e-8f) + 1e-8f);
            float zh = 1.f / (1.f + expf(-((L0 + g0 - g1) / temp)));
            float sg = 1.f / (1.f + expf(-L0));
            out[(size_t)t * CCH + c]                    = zh;
            out[(size_t)TD * CCH + (size_t)t * CCH + c] = sg;
        }
    }
}

// ============================================================
// launch
// ============================================================
extern "C" void kernel_launch(void* const* d_in, const int* in_sizes, int n_in,
                              void* d_out, int out_size)
{
    const float* S_e    = (const float*)d_in[0];
    const float* S_i    = (const float*)d_in[1];
    const float* Z_obs  = (const float*)d_in[2];
    const float* temp   = (const float*)d_in[3];
    const float* u      = (const float*)d_in[4];
    const float* C_se   = (const float*)d_in[5];
    const float* C_si   = (const float*)d_in[6];
    const float* W_syn  = (const float*)d_in[7];
    const float* W_obs  = (const float*)d_in[8];
    const float* Theta  = (const float*)d_in[9];
    float* out = (float*)d_out;
    (void)in_sizes; (void)n_in; (void)out_size;

    cudaFuncSetAttribute(gemm_bf16_kernel, cudaFuncAttributeMaxDynamicSharedMemorySize, GSMEM_BYTES);

    float* syn_e_ptr; float* syn_i_ptr;
    cudaGetSymbolAddress((void**)&syn_e_ptr, g_syn_e);
    cudaGetSymbolAddress((void**)&syn_i_ptr, g_syn_i);

    build_kernels_kernel<<<2, 256>>>(W_syn, W_obs);

    dim3 gg((TD + GBM - 1) / GBM, 2);          // 391 x 2 (E and I fused)
    gemm_bf16_kernel<<<gg, 256, GSMEM_BYTES>>>(S_e, C_se, syn_e_ptr,
                                               S_i, C_si, syn_i_ptr);

    dim3 cg(CCH, (TD + TT - 1) / TT);          // 63 x 25
    conv_finish_kernel<<<cg, 256>>>(Z_obs, u, Theta, temp, out);
}

// round 8
// speedup vs baseline: 3.3963x; 1.5715x over previous
#include <cuda_runtime.h>
#include <cstdint>
#include <math.h>

// ---------------- problem constants ----------------
#define TD      50000
#define E_NO    2000
#define I_NO    500
#define CCH     63
#define TN      200
#define OBS_LEN 401
#define NB      13
#define PI_F    3.14159265358979323846f

// ---------------- device scratch ----------------
__device__ float g_ek[CCH * TN];
__device__ float g_ik[CCH * TN];
__device__ float g_ok[CCH * (OBS_LEN + 3)];
__device__ float g_syn_e[CCH * TD];
__device__ float g_syn_i[CCH * TD];

// pack two fp32 -> bf16x2 (lo = first, hi = second)
__device__ __forceinline__ uint32_t bf2(float lo, float hi) {
    uint32_t r;
    asm("cvt.rn.bf16x2.f32 %0, %1, %2;" : "=r"(r) : "f"(hi), "f"(lo));
    return r;
}

// ============================================================
// Kernel 0: build temporal kernels. One block per time index j
//   (601 blocks); threads 0..12 compute the raised-cosine basis
//   (fp32 MUFU), threads 0..62 do the per-channel dots.
// ============================================================
__global__ __launch_bounds__(64) void build_kernels_kernel(
    const float* __restrict__ W_syn,   // [63][13][2]
    const float* __restrict__ W_obs)   // [63][25]
{
    __shared__ float bs[NB];
    const int blk = blockIdx.x;
    const int tid = threadIdx.x;

    if (blk < TN) {
        const int j = blk;
        if (tid < NB) {
            float raw = 5.f * logf((float)j + 1.f + 1e-8f);
            float phi = 0.5f * PI_F * (float)tid;
            float v = 0.5f * cosf(raw - phi) + 0.5f;
            if (raw < phi - PI_F || raw > phi + PI_F) v = 0.f;   // basis is 0 at cutoff -> flip-safe
            bs[tid] = v;
        }
        __syncthreads();
        if (tid < CCH) {
            const int c = tid;
            float ae = 0.f, ai = 0.f;
            #pragma unroll
            for (int b = 0; b < NB; b++) {
                ae = fmaf(W_syn[(c * NB + b) * 2 + 0], bs[b], ae);
                ai = fmaf(W_syn[(c * NB + b) * 2 + 1], bs[b], ai);
            }
            g_ek[c * TN + j] = ae;
            g_ik[c * TN + j] = ai;
        }
    } else {
        const int j = blk - TN;            // 0..400
        if (tid < NB) {
            float xo = (float)(j - TN);
            float raw = 5.f * logf(fabsf(xo) + 1.f + 1e-8f);
            float phi = 0.5f * PI_F * (float)tid;
            float v = 0.5f * cosf(raw - phi) + 0.5f;
            if (raw < phi - PI_F || raw > phi + PI_F) v = 0.f;
            bs[tid] = v;
        }
        __syncthreads();
        if (tid < CCH) {
            const int c = tid;
            float a = W_obs[c * 25 + 0] * bs[0];
            #pragma unroll
            for (int b = 1; b < NB; b++) {
                if (j >= TN) a = fmaf(W_obs[c * 25 + 2 * b - 1], bs[b], a);
                if (j <= TN) a = fmaf(W_obs[c * 25 + 2 * b    ], bs[b], a);
            }
            g_ok[c * (OBS_LEN + 3) + j] = a;
        }
    }
}

// ============================================================
// Kernel 1: bf16 mma.sync GEMM  outT[c][t] = sum_k A[t][k]*Cs[c+1][k]
//   BM=128, BN=64, BK=32 floats; 8 warps 4(M)x2(N), warp tile 32x32
//   m16n8k16 bf16; fp32 LDG -> cvt.bf16x2 -> STS, reg double buffer
//   blockIdx.y selects the E (y=0) or I (y=1) problem
// ============================================================
#define GBM     128
#define GBK     32
#define APW     20                        // smem row pitch in 32-bit words (80B)
#define AW      (128 * APW)               // A stage words
#define BW      (64 * APW)                // B stage words
#define STW     (AW + BW)                 // 3840 words / stage
#define GSMEM_BYTES (64 * 132 * 4)        // 33792 B (> 2*STW*4 = 30720)

__global__ __launch_bounds__(256) void gemm_bf16_kernel(
    const float* __restrict__ Ae, const float* __restrict__ Cse, float* __restrict__ oute,
    const float* __restrict__ Ai, const float* __restrict__ Csi, float* __restrict__ outi)
{
    extern __shared__ float smf[];
    uint32_t* smw = reinterpret_cast<uint32_t*>(smf);

    const float* A; const float* Cs; float* outT; int K;
    if (blockIdx.y == 0) { A = Ae; Cs = Cse; outT = oute; K = E_NO; }
    else                 { A = Ai; Cs = Csi; outT = outi; K = I_NO; }
    const int S = (K + GBK - 1) / GBK;

    const int tid  = threadIdx.x;
    const int wid  = tid >> 5;
    const int lane = tid & 31;
    const int g    = lane >> 2;
    const int t4   = lane & 3;
    const int wm   = (wid & 3) * 32;
    const int wn   = (wid >> 2) * 32;
    const int bm   = blockIdx.x * GBM;

    float acc[2][4][4];
    #pragma unroll
    for (int mi = 0; mi < 2; mi++)
        #pragma unroll
        for (int ni = 0; ni < 4; ni++)
            #pragma unroll
            for (int r = 0; r < 4; r++) acc[mi][ni][r] = 0.f;

    float4 ra[4], rb[2];

    auto ldg_stage = [&](int s) {
        const int k0 = s * GBK;
        #pragma unroll
        for (int j = 0; j < 4; j++) {
            int idx = tid + 256 * j, r = idx >> 3, q = idx & 7, k = k0 + q * 4;
            float4 v = make_float4(0.f, 0.f, 0.f, 0.f);
            if ((bm + r < TD) && (k + 4 <= K))
                v = *reinterpret_cast<const float4*>(A + (size_t)(bm + r) * K + k);
            ra[j] = v;
        }
        #pragma unroll
        for (int j = 0; j < 2; j++) {
            int idx = tid + 256 * j, r = idx >> 3, q = idx & 7, k = k0 + q * 4;
            float4 v = make_float4(0.f, 0.f, 0.f, 0.f);
            if ((r < CCH) && (k + 4 <= K))
                v = *reinterpret_cast<const float4*>(Cs + (size_t)(r + 1) * K + k);
            rb[j] = v;
        }
    };
    auto sts_stage = [&](int buf) {
        uint32_t* ab = smw + buf * STW;
        uint32_t* bb = ab + AW;
        #pragma unroll
        for (int j = 0; j < 4; j++) {
            int idx = tid + 256 * j, r = idx >> 3, q = idx & 7;
            uint2* p = reinterpret_cast<uint2*>(ab + r * APW + q * 2);
            *p = make_uint2(bf2(ra[j].x, ra[j].y), bf2(ra[j].z, ra[j].w));
        }
        #pragma unroll
        for (int j = 0; j < 2; j++) {
            int idx = tid + 256 * j, r = idx >> 3, q = idx & 7;
            uint2* p = reinterpret_cast<uint2*>(bb + r * APW + q * 2);
            *p = make_uint2(bf2(rb[j].x, rb[j].y), bf2(rb[j].z, rb[j].w));
        }
    };
    auto compute = [&](int buf) {
        const uint32_t* As = smw + buf * STW;
        const uint32_t* Bs = As + AW;
        #pragma unroll
        for (int ks = 0; ks < 2; ks++) {
            const int kw = ks * 8;
            uint32_t af[2][4];
            #pragma unroll
            for (int mi = 0; mi < 2; mi++) {
                int r = wm + mi * 16 + g;
                af[mi][0] = As[(r)     * APW + kw + t4];
                af[mi][1] = As[(r + 8) * APW + kw + t4];
                af[mi][2] = As[(r)     * APW + kw + 4 + t4];
                af[mi][3] = As[(r + 8) * APW + kw + 4 + t4];
            }
            uint32_t bf[4][2];
            #pragma unroll
            for (int ni = 0; ni < 4; ni++) {
                int n = wn + ni * 8 + g;
                bf[ni][0] = Bs[n * APW + kw + t4];
                bf[ni][1] = Bs[n * APW + kw + 4 + t4];
            }
            #pragma unroll
            for (int mi = 0; mi < 2; mi++)
                #pragma unroll
                for (int ni = 0; ni < 4; ni++) {
                    asm volatile(
                        "mma.sync.aligned.m16n8k16.row.col.f32.bf16.bf16.f32 "
                        "{%0,%1,%2,%3}, {%4,%5,%6,%7}, {%8,%9}, {%0,%1,%2,%3};"
                        : "+f"(acc[mi][ni][0]), "+f"(acc[mi][ni][1]),
                          "+f"(acc[mi][ni][2]), "+f"(acc[mi][ni][3])
                        : "r"(af[mi][0]), "r"(af[mi][1]), "r"(af[mi][2]), "r"(af[mi][3]),
                          "r"(bf[ni][0]), "r"(bf[ni][1]));
                }
        }
    };

    // ---- register double-buffered pipeline ----
    ldg_stage(0);
    sts_stage(0);
    __syncthreads();

    for (int s = 0; s < S; s++) {
        const bool have_next = (s + 1 < S);
        if (have_next) ldg_stage(s + 1);
        compute(s & 1);
        __syncthreads();
        if (have_next) {
            sts_stage((s + 1) & 1);
            __syncthreads();
        }
    }

    // ---- transpose epilogue through smem -> coalesced [c][t] stores ----
    #pragma unroll
    for (int mi = 0; mi < 2; mi++)
        #pragma unroll
        for (int ni = 0; ni < 4; ni++) {
            int n0 = wn + ni * 8 + 2 * t4;
            int m0 = wm + mi * 16 + g;
            smf[(n0)     * 132 + m0]     = acc[mi][ni][0];
            smf[(n0 + 1) * 132 + m0]     = acc[mi][ni][1];
            smf[(n0)     * 132 + m0 + 8] = acc[mi][ni][2];
            smf[(n0 + 1) * 132 + m0 + 8] = acc[mi][ni][3];
        }
    __syncthreads();
    for (int idx = tid; idx < 64 * 128; idx += 256) {
        int c  = idx >> 7;
        int tl = idx & 127;
        int t  = bm + tl;
        if (c < CCH && t < TD)
            outT[(size_t)c * TD + t] = smf[c * 132 + tl];
    }
}

// ============================================================
// Kernel 2: temporal convs + Gumbel-softmax / sigmoid epilogue
//   sliding register windows: 1 float4 LDS per array per 4 taps
// ============================================================
#define TT 2048

__global__ __launch_bounds__(256) void conv_finish_kernel(
    const float* __restrict__ Z,
    const float* __restrict__ u,
    const float* __restrict__ Theta,
    const float* __restrict__ temp_p,
    float* __restrict__ out)
{
    __shared__ __align__(16) float se_s[TT + TN + 16];
    __shared__ __align__(16) float si_s[TT + TN + 16];
    __shared__ __align__(16) float z_s [TT + 2 * TN + 16];
    __shared__ __align__(16) float ek_s[TN];
    __shared__ __align__(16) float ik_s[TN];
    __shared__ __align__(16) float ok_s[OBS_LEN + 3];

    const int c   = blockIdx.x;        // channel fastest
    const int t0  = blockIdx.y * TT;
    const int tid = threadIdx.x;

    const float* se_g = g_syn_e + (size_t)c * TD;
    const float* si_g = g_syn_i + (size_t)c * TD;

    for (int i = tid; i < TT + TN + 16; i += 256) {
        int t = t0 - (TN - 1) + i;
        float ve = 0.f, vi = 0.f;
        if (t >= 0 && t < TD) { ve = se_g[t]; vi = si_g[t]; }
        se_s[i] = ve; si_s[i] = vi;
    }
    for (int i = tid; i < TT + 2 * TN + 16; i += 256) {
        int t = t0 - TN + i;
        z_s[i] = (t >= 0 && t < TD) ? Z[t] : 0.f;
    }
    for (int j = tid; j < TN; j += 256) {
        ek_s[j] = g_ek[c * TN + j];
        ik_s[j] = g_ik[c * TN + j];
    }
    for (int j = tid; j < OBS_LEN; j += 256)
        ok_s[j] = g_ok[c * (OBS_LEN + 3) + j];
    __syncthreads();

    const int tl0 = tid * 8;
    float acc[8];
    #pragma unroll
    for (int i = 0; i < 8; i++) acc[i] = 0.f;

    // ---------- causal e/i convs (sliding register window) ----------
    {
        float ew[12], iw[12];
        #pragma unroll
        for (int x = 0; x < 3; x++) {
            float4 a = *reinterpret_cast<const float4*>(&se_s[tl0 + 4 * x]);
            float4 b = *reinterpret_cast<const float4*>(&si_s[tl0 + 4 * x]);
            ew[4 * x] = a.x; ew[4 * x + 1] = a.y; ew[4 * x + 2] = a.z; ew[4 * x + 3] = a.w;
            iw[4 * x] = b.x; iw[4 * x + 1] = b.y; iw[4 * x + 2] = b.z; iw[4 * x + 3] = b.w;
        }
        #pragma unroll 5
        for (int p = 0; p < 50; p++) {
            float4 we4 = *reinterpret_cast<const float4*>(&ek_s[196 - 4 * p]);
            float4 wi4 = *reinterpret_cast<const float4*>(&ik_s[196 - 4 * p]);
            float4 ne  = *reinterpret_cast<const float4*>(&se_s[tl0 + 12 + 4 * p]);
            float4 ni  = *reinterpret_cast<const float4*>(&si_s[tl0 + 12 + 4 * p]);
            const float we[4] = {we4.x, we4.y, we4.z, we4.w};
            const float wi[4] = {wi4.x, wi4.y, wi4.z, wi4.w};
            #pragma unroll
            for (int dj = 0; dj < 4; dj++) {
                #pragma unroll
                for (int i = 0; i < 8; i++) {
                    acc[i] = fmaf(ew[i + 3 - dj], we[dj], acc[i]);
                    acc[i] = fmaf(iw[i + 3 - dj], wi[dj], acc[i]);
                }
            }
            #pragma unroll
            for (int x = 0; x < 8; x++) { ew[x] = ew[x + 4]; iw[x] = iw[x + 4]; }
            ew[8] = ne.x; ew[9] = ne.y; ew[10] = ne.z; ew[11] = ne.w;
            iw[8] = ni.x; iw[9] = ni.y; iw[10] = ni.z; iw[11] = ni.w;
        }
    }

    // ---------- obs conv ----------
    {
        float zw[12];
        #pragma unroll
        for (int x = 0; x < 3; x++) {
            float4 a = *reinterpret_cast<const float4*>(&z_s[tl0 + 4 * x]);
            zw[4 * x] = a.x; zw[4 * x + 1] = a.y; zw[4 * x + 2] = a.z; zw[4 * x + 3] = a.w;
        }
        {   // tail tap j = 400 -> z index tl0 + i
            float w = ok_s[400];
            #pragma unroll
            for (int i = 0; i < 8; i++) acc[i] = fmaf(zw[i], w, acc[i]);
        }
        #pragma unroll 5
        for (int p = 0; p < 100; p++) {
            float4 w4 = *reinterpret_cast<const float4*>(&ok_s[396 - 4 * p]);
            float4 nz = *reinterpret_cast<const float4*>(&z_s[tl0 + 12 + 4 * p]);
            const float w[4] = {w4.x, w4.y, w4.z, w4.w};
            #pragma unroll
            for (int dj = 0; dj < 4; dj++) {
                #pragma unroll
                for (int i = 0; i < 8; i++)
                    acc[i] = fmaf(zw[i + 4 - dj], w[dj], acc[i]);
            }
            #pragma unroll
            for (int x = 0; x < 8; x++) zw[x] = zw[x + 4];
            zw[8] = nz.x; zw[9] = nz.y; zw[10] = nz.z; zw[11] = nz.w;
        }
    }

    // ---------- epilogue ----------
    const float th   = Theta[c];
    const float temp = *temp_p;
    #pragma unroll
    for (int i = 0; i < 8; i++) {
        int t = t0 + tl0 + i;
        if (t < TD) {
            float L0 = acc[i] + th;
            float2 uv = *reinterpret_cast<const float2*>(&u[((size_t)t * CCH + c) * 2]);
            float g0 = -logf(-logf(uv.x + 1e-8f) + 1e-8f);
            float g1 = -logf(-logf(uv.y + 1e-8f) + 1e-8f);
            float zh = 1.f / (1.f + expf(-((L0 + g0 - g1) / temp)));
            float sg = 1.f / (1.f + expf(-L0));
            out[(size_t)t * CCH + c]                    = zh;
            out[(size_t)TD * CCH + (size_t)t * CCH + c] = sg;
        }
    }
}

// ============================================================
// launch
// ============================================================
extern "C" void kernel_launch(void* const* d_in, const int* in_sizes, int n_in,
                              void* d_out, int out_size)
{
    const float* S_e    = (const float*)d_in[0];
    const float* S_i    = (const float*)d_in[1];
    const float* Z_obs  = (const float*)d_in[2];
    const float* temp   = (const float*)d_in[3];
    const float* u      = (const float*)d_in[4];
    const float* C_se   = (const float*)d_in[5];
    const float* C_si   = (const float*)d_in[6];
    const float* W_syn  = (const float*)d_in[7];
    const float* W_obs  = (const float*)d_in[8];
    const float* Theta  = (const float*)d_in[9];
    float* out = (float*)d_out;
    (void)in_sizes; (void)n_in; (void)out_size;

    cudaFuncSetAttribute(gemm_bf16_kernel, cudaFuncAttributeMaxDynamicSharedMemorySize, GSMEM_BYTES);

    float* syn_e_ptr; float* syn_i_ptr;
    cudaGetSymbolAddress((void**)&syn_e_ptr, g_syn_e);
    cudaGetSymbolAddress((void**)&syn_i_ptr, g_syn_i);

    build_kernels_kernel<<<TN + OBS_LEN, 64>>>(W_syn, W_obs);

    dim3 gg((TD + GBM - 1) / GBM, 2);          // 391 x 2 (E and I fused)
    gemm_bf16_kernel<<<gg, 256, GSMEM_BYTES>>>(S_e, C_se, syn_e_ptr,
                                               S_i, C_si, syn_i_ptr);

    dim3 cg(CCH, (TD + TT - 1) / TT);          // 63 x 25
    conv_finish_kernel<<<cg, 256>>>(Z_obs, u, Theta, temp, out);
}